// round 6
// baseline (speedup 1.0000x reference)
#include <cuda_runtime.h>
#include <cstdint>

// Problem constants (fixed by the reference).
#define IMAGE_TOKEN_ID 31999
#define B_DIM 4
#define L_DIM 1024
#define D_DIM 2048
#define NUM_VIS 576
#define NEW_LEN (L_DIM - 1 + NUM_VIS)      // 1599
#define NROWS  (B_DIM * NEW_LEN)           // 6396

// Scratch: per-output-row source pointer (device global: no allocation).
__device__ const float4* g_src[6400];

// ---------------------------------------------------------------------------
// Setup kernel: find the image-token position per batch row (each block scans
// the 16 KB of input_ids redundantly — trivial), then compute the source
// pointer for each output row and optionally write position_ids.
// One launch, 25 blocks x 256 threads covers all 6396 rows.
// ---------------------------------------------------------------------------
__global__ __launch_bounds__(256)
void setup_kernel(const int* __restrict__ input_ids,
                  const float4* __restrict__ visual,   // [B, NUM_VIS, D/4]
                  const float4* __restrict__ embed,    // [32768, D/4]
                  float* __restrict__ out_flat,
                  int write_pos)
{
    __shared__ int s_ip[B_DIM];
    const int t = threadIdx.x;

    // Phase 1: locate the unique image token per batch row.
    for (int i = t; i < B_DIM * L_DIM; i += 256) {
        if (input_ids[i] == IMAGE_TOKEN_ID) s_ip[i / L_DIM] = i % L_DIM;
    }
    __syncthreads();

    // Phase 2: per-output-row source pointer.
    const int row = blockIdx.x * 256 + t;
    if (row < NROWS) {
        const int b  = row / NEW_LEN;
        const int j  = row - b * NEW_LEN;
        const int ip = s_ip[b];

        const float4* src;
        if (j >= ip && j < ip + NUM_VIS) {
            src = visual + ((size_t)b * NUM_VIS + (size_t)(j - ip)) * (D_DIM / 4);
        } else {
            const int l   = (j < ip) ? j : j - (NUM_VIS - 1);
            const int tok = input_ids[b * L_DIM + l];
            src = embed + (size_t)tok * (D_DIM / 4);
        }
        g_src[row] = src;

        if (write_pos) {
            out_flat[(size_t)NROWS * D_DIM + row] = (float)j;
        }
    }
}

// ---------------------------------------------------------------------------
// Merge kernel: 2 output rows per block, 256 threads. Pointer loads hit L2
// (written by setup_kernel); then 4 independent LDG.128 + 4 STG.128 per
// thread — MLP 4, no dependent gather chain, full occupancy (~34 regs).
// ---------------------------------------------------------------------------
__global__ __launch_bounds__(256)
void merge_kernel(float4* __restrict__ out)
{
    const int t    = threadIdx.x;
    const int row0 = blockIdx.x * 2;

    const float4* __restrict__ p0 = g_src[row0];
    const float4* __restrict__ p1 = g_src[row0 + 1];

    // 4 independent 128-bit loads (front-batched -> high MLP_p1).
    const float4 v0 = __ldg(p0 + t);
    const float4 v1 = __ldg(p0 + t + 256);
    const float4 v2 = __ldg(p1 + t);
    const float4 v3 = __ldg(p1 + t + 256);

    float4* d = out + (size_t)row0 * (D_DIM / 4);
    d[t]             = v0;
    d[t + 256]       = v1;
    d[t + 512]       = v2;
    d[t + 512 + 256] = v3;
}

// ---------------------------------------------------------------------------
// Launch contract
// inputs (metadata order): input_ids [B,L] int32, visual_tokens [B,NUM_VIS,D]
// float32, embed_table [32768,D] float32.
// output: merged [B,NEW_LEN,D] float32 (+ optionally position_ids appended).
// ---------------------------------------------------------------------------
extern "C" void kernel_launch(void* const* d_in, const int* in_sizes, int n_in,
                              void* d_out, int out_size)
{
    const int*    input_ids = (const int*)   d_in[0];
    const float4* visual    = (const float4*)d_in[1];
    const float4* embed     = (const float4*)d_in[2];

    float4* out      = (float4*)d_out;
    float*  out_flat = (float*) d_out;

    const long long merged_elems = (long long)NROWS * D_DIM;
    const int write_pos = (out_size > merged_elems) ? 1 : 0;

    setup_kernel<<<(NROWS + 255) / 256, 256>>>(input_ids, visual, embed,
                                               out_flat, write_pos);
    merge_kernel<<<NROWS / 2, 256>>>(out);
}

// round 11
// speedup vs baseline: 1.0845x; 1.0845x over previous
#include <cuda_runtime.h>
#include <cstdint>

// Problem constants (fixed by the reference).
#define IMAGE_TOKEN_ID 31999
#define B_DIM 4
#define L_DIM 1024
#define D_DIM 2048
#define NUM_VIS 576
#define NEW_LEN (L_DIM - 1 + NUM_VIS)      // 1599
#define NROWS  (B_DIM * NEW_LEN)           // 6396

// Scratch: per-batch image-token position.
__device__ int g_img_pos[B_DIM];

// 256-bit load with L2 evict_last. sm_103a ptxas only accepts the
// L2::evict_last qualifier on .v8.b32 / .v4.b64 (256-bit) loads — which also
// halves LDG count. Requires 32-byte alignment (holds: rows are 8 KB strided,
// thread offset is t*32).
__device__ __forceinline__ void ldg256_el(const void* p, ulonglong4& v) {
    asm("ld.global.nc.L2::evict_last.v4.b64 {%0,%1,%2,%3}, [%4];"
        : "=l"(v.x), "=l"(v.y), "=l"(v.z), "=l"(v.w) : "l"(p));
}

// ---------------------------------------------------------------------------
// Kernel 1: locate the (unique) image token per batch row. 4096 int32 scan.
// ---------------------------------------------------------------------------
__global__ void find_img_pos_kernel(const int* __restrict__ input_ids) {
    int idx = blockIdx.x * blockDim.x + threadIdx.x;
    if (idx < B_DIM * L_DIM) {
        if (input_ids[idx] == IMAGE_TOKEN_ID) {
            g_img_pos[idx / L_DIM] = idx % L_DIM;
        }
    }
}

// ---------------------------------------------------------------------------
// Kernel 2: merged-row copy. One block per output row, 256 threads, each
// thread moves one contiguous 32-byte chunk (256 x 32B = 8KB row) via a
// single 256-bit evict_last load + two 128-bit stores.
// ---------------------------------------------------------------------------
__global__ __launch_bounds__(256, 8)
void merge_kernel(const int* __restrict__ input_ids,
                  const char* __restrict__ visual,        // [B, NUM_VIS, D] f32
                  const char* __restrict__ embed,         // [32768, D] f32
                  char* __restrict__ out,                 // [B, NEW_LEN, D] f32
                  float* __restrict__ out_flat,
                  int write_pos)
{
    const int row = blockIdx.x;                 // 0 .. NROWS-1
    const int b = row / NEW_LEN;
    const int j = row - b * NEW_LEN;
    const int ip = g_img_pos[b];

    const size_t ROW_BYTES = (size_t)D_DIM * 4;   // 8192

    const char* src;
    if (j >= ip && j < ip + NUM_VIS) {
        src = visual + ((size_t)b * NUM_VIS + (size_t)(j - ip)) * ROW_BYTES;
    } else {
        const int l = (j < ip) ? j : j - (NUM_VIS - 1);
        const int tok = __ldg(input_ids + b * L_DIM + l);
        src = embed + (size_t)tok * ROW_BYTES;
    }

    const int t = threadIdx.x;
    ulonglong4 v;
    ldg256_el(src + (size_t)t * 32, v);

    char* dst = out + (size_t)row * ROW_BYTES + (size_t)t * 32;
    ulonglong2* d2 = (ulonglong2*)dst;
    d2[0] = make_ulonglong2(v.x, v.y);
    d2[1] = make_ulonglong2(v.z, v.w);

    if (write_pos && t == 0) {
        out_flat[(size_t)NROWS * D_DIM + row] = (float)j;
    }
}

// ---------------------------------------------------------------------------
// Launch contract
// inputs (metadata order): input_ids [B,L] int32, visual_tokens [B,NUM_VIS,D]
// float32, embed_table [32768,D] float32.
// output: merged [B,NEW_LEN,D] float32 (+ optionally position_ids appended).
// ---------------------------------------------------------------------------
extern "C" void kernel_launch(void* const* d_in, const int* in_sizes, int n_in,
                              void* d_out, int out_size)
{
    const int*  input_ids = (const int*) d_in[0];
    const char* visual    = (const char*)d_in[1];
    const char* embed     = (const char*)d_in[2];

    char*  out      = (char*) d_out;
    float* out_flat = (float*)d_out;

    const long long merged_elems = (long long)NROWS * D_DIM;
    const int write_pos = (out_size > merged_elems) ? 1 : 0;

    find_img_pos_kernel<<<(B_DIM * L_DIM + 255) / 256, 256>>>(input_ids);
    merge_kernel<<<NROWS, 256>>>(input_ids, visual, embed,
                                 out, out_flat, write_pos);
}

// round 15
// speedup vs baseline: 1.3988x; 1.2899x over previous
#include <cuda_runtime.h>
#include <cstdint>

// Problem constants (fixed by the reference).
#define IMAGE_TOKEN_ID 31999
#define B_DIM 4
#define L_DIM 1024
#define D_DIM 2048
#define NUM_VIS 576
#define NEW_LEN (L_DIM - 1 + NUM_VIS)      // 1599
#define NROWS  (B_DIM * NEW_LEN)           // 6396

#define GRID_BLOCKS 1216                   // 152 SMs x 8 CTAs -> one wave

// ---------------------------------------------------------------------------
// Single fused persistent kernel.
// Phase 1: every block scans all 4096 input_ids (16 KB; L1-resident after the
//          first block on each SM) to find the 4 image-token positions.
// Phase 2: grid-stride over the 6396 output rows; each iteration copies one
//          8 KB row (256 threads x 2 float4 loads + 2 stores).
// One launch, one wave: removes find-kernel launch overhead (~2.5us) and
// 4 wave transitions (~2-4us) that R1/R11 paid.
// ---------------------------------------------------------------------------
__global__ __launch_bounds__(256, 8)
void fused_merge_kernel(const int* __restrict__ input_ids,
                        const float4* __restrict__ visual,   // [B, NUM_VIS, D/4]
                        const float4* __restrict__ embed,    // [32768, D/4]
                        float4* __restrict__ out,            // [B, NEW_LEN, D/4]
                        float* __restrict__ out_flat,
                        int write_pos)
{
    __shared__ int s_ip[B_DIM];
    const int t = threadIdx.x;

    // Phase 1: scan input_ids. 4096 ints = 1024 int4; 256 threads x 4 int4.
    const int4* ids4 = (const int4*)input_ids;
    #pragma unroll
    for (int k = 0; k < 4; k++) {
        const int idx4 = t + k * 256;          // 0..1023
        const int4 v = __ldg(ids4 + idx4);
        const int base = idx4 * 4;
        if (v.x == IMAGE_TOKEN_ID) s_ip[ base      / L_DIM] =  base      % L_DIM;
        if (v.y == IMAGE_TOKEN_ID) s_ip[(base + 1) / L_DIM] = (base + 1) % L_DIM;
        if (v.z == IMAGE_TOKEN_ID) s_ip[(base + 2) / L_DIM] = (base + 2) % L_DIM;
        if (v.w == IMAGE_TOKEN_ID) s_ip[(base + 3) / L_DIM] = (base + 3) % L_DIM;
    }
    __syncthreads();

    // Phase 2: persistent grid-stride over output rows.
    for (int row = blockIdx.x; row < NROWS; row += GRID_BLOCKS) {
        const int b  = row / NEW_LEN;
        const int j  = row - b * NEW_LEN;
        const int ip = s_ip[b];

        const float4* src;
        if (j >= ip && j < ip + NUM_VIS) {
            src = visual + ((size_t)b * NUM_VIS + (size_t)(j - ip)) * (D_DIM / 4);
        } else {
            const int l   = (j < ip) ? j : j - (NUM_VIS - 1);
            const int tok = __ldg(input_ids + b * L_DIM + l);   // L1-hit
            src = embed + (size_t)tok * (D_DIM / 4);
        }

        const float4 v0 = __ldg(src + t);
        const float4 v1 = __ldg(src + t + 256);
        float4* dst = out + (size_t)row * (D_DIM / 4);
        dst[t]       = v0;
        dst[t + 256] = v1;

        if (write_pos && t == 0) {
            out_flat[(size_t)NROWS * D_DIM + row] = (float)j;
        }
    }
}

// ---------------------------------------------------------------------------
// Launch contract
// inputs (metadata order): input_ids [B,L] int32, visual_tokens [B,NUM_VIS,D]
// float32, embed_table [32768,D] float32.
// output: merged [B,NEW_LEN,D] float32 (+ optionally position_ids appended).
// ---------------------------------------------------------------------------
extern "C" void kernel_launch(void* const* d_in, const int* in_sizes, int n_in,
                              void* d_out, int out_size)
{
    const int*    input_ids = (const int*)   d_in[0];
    const float4* visual    = (const float4*)d_in[1];
    const float4* embed     = (const float4*)d_in[2];

    float4* out      = (float4*)d_out;
    float*  out_flat = (float*) d_out;

    const long long merged_elems = (long long)NROWS * D_DIM;
    const int write_pos = (out_size > merged_elems) ? 1 : 0;

    fused_merge_kernel<<<GRID_BLOCKS, 256>>>(input_ids, visual, embed,
                                             out, out_flat, write_pos);
}